// round 5
// baseline (speedup 1.0000x reference)
#include <cuda_runtime.h>

#define T_STEPS 2048
#define HID 32
#define OUT_DIM 8
#define BATCH 512

typedef unsigned long long ull;

// 512 x 2048 x 128 fp32 staging for the precomputed layer-1 input projection
__device__ float g_xg[(size_t)BATCH * T_STEPS * 128];

// ---- packed fp32x2 helpers (sm_100+) ----
__device__ __forceinline__ void fma2(ull &d, ull a, ull b) {
    asm("fma.rn.f32x2 %0, %1, %2, %0;" : "+l"(d) : "l"(a), "l"(b));
}
__device__ __forceinline__ ull add2(ull a, ull b) {
    ull r; asm("add.rn.f32x2 %0, %1, %2;" : "=l"(r) : "l"(a), "l"(b)); return r;
}
__device__ __forceinline__ float red2(ull a) {
    float lo, hi;
    asm("mov.b64 {%0,%1}, %2;" : "=f"(lo), "=f"(hi) : "l"(a));
    return lo + hi;
}
__device__ __forceinline__ void lds2(ull &a, ull &b, unsigned addr) {
    asm volatile("ld.shared.v2.b64 {%0,%1}, [%2];" : "=l"(a), "=l"(b) : "r"(addr));
}

__device__ __forceinline__ float sigm(float x) {
    return __fdividef(1.0f, 1.0f + __expf(-x));
}
__device__ __forceinline__ float tanh_(float x) {
    float e = __expf(2.0f * fminf(x, 15.0f));
    return __fdividef(e - 1.0f, e + 1.0f);
}

// dot of a register-resident 32-wide row (16 packed pairs) with a 32-float smem
// vector; all lanes read the SAME smem address -> broadcast, conflict-free.
__device__ __forceinline__ void dot32(const ull *__restrict__ w, unsigned saddr,
                                      ull &a0, ull &a1, ull &a2, ull &a3) {
#pragma unroll
    for (int i = 0; i < 4; i++) {
        ull p0, p1, p2, p3;
        lds2(p0, p1, saddr + i * 32);
        lds2(p2, p3, saddr + i * 32 + 16);
        fma2(a0, w[4 * i + 0], p0);
        fma2(a1, w[4 * i + 1], p1);
        fma2(a2, w[4 * i + 2], p2);
        fma2(a3, w[4 * i + 3], p3);
    }
}

// ===================== prepass: xg[b][t][r] = (bih0+bhh0)[r] + Wih0[r,:].x[b,t,:]
// grid (8, 512), block 128. Thread j owns output row r=j for a tile of 32 timesteps.
__global__ void __launch_bounds__(128) xg_prepass(
    const float *__restrict__ X, const float *__restrict__ Wih0,
    const float *__restrict__ bih0, const float *__restrict__ bhh0)
{
    __shared__ __align__(16) float xs[32][32];   // 32 timesteps x 32 features
    const int j = threadIdx.x;
    const int b = blockIdx.y;
    const int t0 = blockIdx.x * 256;

    ull w[16];
    {
        const ull *p = (const ull *)(Wih0 + j * 32);
#pragma unroll
        for (int i = 0; i < 16; i++) w[i] = p[i];
    }
    const float bias = bih0[j] + bhh0[j];
    const unsigned xs_base = (unsigned)__cvta_generic_to_shared(&xs[0][0]);

    for (int tile = 0; tile < 8; tile++) {
        const int tt = t0 + tile * 32;
        __syncthreads();                          // xs reuse guard
        const float *src = X + ((size_t)b * T_STEPS + tt) * 32;
#pragma unroll
        for (int i = 0; i < 8; i++) ((float *)xs)[i * 128 + j] = src[i * 128 + j];
        __syncthreads();

        ull acc[32];
#pragma unroll
        for (int t = 0; t < 32; t++) acc[t] = 0ull;
#pragma unroll
        for (int kp = 0; kp < 16; kp++) {
#pragma unroll
            for (int t = 0; t < 32; t++) {
                ull xv;
                asm volatile("ld.shared.b64 %0, [%1];"
                             : "=l"(xv) : "r"(xs_base + (unsigned)(t * 128 + kp * 8)));
                fma2(acc[t], w[kp], xv);
            }
        }
        float *dst = g_xg + ((size_t)b * T_STEPS + tt) * 128 + j;
#pragma unroll
        for (int t = 0; t < 32; t++) dst[t * 128] = red2(acc[t]) + bias;
    }
}

// ===================== recurrent kernel: layer-pipelined, 1 barrier/step
// block 256: warps 0-3 = layer1 (step k), warps 4-7 = layer2 (step k-1)
__global__ void __launch_bounds__(256, 2) lstm_rec(
    const float *__restrict__ Whh0,
    const float *__restrict__ Wih1, const float *__restrict__ Whh1,
    const float *__restrict__ bih1, const float *__restrict__ bhh1,
    const float *__restrict__ Wfc, const float *__restrict__ bfc,
    float *__restrict__ out)
{
    __shared__ __align__(16) float h1s[2][32];
    __shared__ __align__(16) float h2s[2][32];

    const int tid = threadIdx.x;
    const int b = blockIdx.x;
    const int ga = tid >> 7;          // 0 = layer1 group, 1 = layer2 group
    const int j = tid & 127;
    const int gate = j & 3;           // 0=i 1=f 2=g 3=o
    const int u = j >> 2;
    const int r = gate * 32 + u;
    const int lb = (j & 31) & ~3;

    ull w[32];
    float c = 0.0f, bias2 = 0.0f;
    const float *xp = 0;
    float xc = 0.0f, xn = 0.0f;
    if (ga == 0) {
        const ull *p = (const ull *)(Whh0 + r * 32);
#pragma unroll
        for (int i = 0; i < 16; i++) w[i] = p[i];
        xp = g_xg + (size_t)b * T_STEPS * 128 + r;
        xc = __ldg(xp);               // xg(0)
        xn = __ldg(xp + 128);         // xg(1)
    } else {
        const ull *p = (const ull *)(Wih1 + r * 32);
#pragma unroll
        for (int i = 0; i < 16; i++) w[i] = p[i];
        p = (const ull *)(Whh1 + r * 32);
#pragma unroll
        for (int i = 0; i < 16; i++) w[16 + i] = p[i];
        bias2 = bih1[r] + bhh1[r];
    }

    if (tid < 32) { h1s[1][tid] = 0.0f; h2s[1][tid] = 0.0f; }  // h1(-1), h2(-1)
    const unsigned h1b = (unsigned)__cvta_generic_to_shared(&h1s[0][0]);
    const unsigned h2b = (unsigned)__cvta_generic_to_shared(&h2s[0][0]);
    __syncthreads();

#pragma unroll 2
    for (int k = 0; k < T_STEPS; k++) {
        if (ga == 0) {
            // ---- layer 1, step k: h1(k) from h1(k-1) and precomputed xg(k)
            ull a0 = 0ull, a1 = 0ull, a2 = 0ull, a3 = 0ull;
            dot32(w, h1b + (unsigned)(((k + 1) & 1) << 7), a0, a1, a2, a3);
            float g = red2(add2(add2(a0, a1), add2(a2, a3))) + xc;
            float act = (gate == 2) ? tanh_(g) : sigm(g);
            float vi = __shfl_sync(0xffffffffu, act, lb + 0);
            float vf = __shfl_sync(0xffffffffu, act, lb + 1);
            float vg = __shfl_sync(0xffffffffu, act, lb + 2);
            float vo = __shfl_sync(0xffffffffu, act, lb + 3);
            c = fmaf(vf, c, vi * vg);
            float h = vo * tanh_(c);
            if (gate == 0) h1s[k & 1][u] = h;
            // rotate xg prefetch (depth 2)
            xc = xn;
            int kf = k + 2; if (kf > T_STEPS - 1) kf = T_STEPS - 1;
            xn = __ldg(xp + (size_t)kf * 128);
        } else if (k > 0) {
            // ---- layer 2, step k-1: from h1(k-1) and h2(k-2)
            ull a0 = 0ull, a1 = 0ull, a2 = 0ull, a3 = 0ull;
            dot32(w, h1b + (unsigned)(((k + 1) & 1) << 7), a0, a1, a2, a3);      // h1(k-1)
            dot32(w + 16, h2b + (unsigned)((k & 1) << 7), a0, a1, a2, a3);       // h2(k-2)
            float g = red2(add2(add2(a0, a1), add2(a2, a3))) + bias2;
            float act = (gate == 2) ? tanh_(g) : sigm(g);
            float vi = __shfl_sync(0xffffffffu, act, lb + 0);
            float vf = __shfl_sync(0xffffffffu, act, lb + 1);
            float vg = __shfl_sync(0xffffffffu, act, lb + 2);
            float vo = __shfl_sync(0xffffffffu, act, lb + 3);
            c = fmaf(vf, c, vi * vg);
            float h = vo * tanh_(c);
            if (gate == 0) h2s[(k + 1) & 1][u] = h;   // (k-1)&1
        }
        __syncthreads();
    }

    // ---- tail: layer 2, step 2047: h1(2047)@h1s[1], h2(2046)@h2s[0]
    if (ga == 1) {
        ull a0 = 0ull, a1 = 0ull, a2 = 0ull, a3 = 0ull;
        dot32(w, h1b + 128u, a0, a1, a2, a3);
        dot32(w + 16, h2b, a0, a1, a2, a3);
        float g = red2(add2(add2(a0, a1), add2(a2, a3))) + bias2;
        float act = (gate == 2) ? tanh_(g) : sigm(g);
        float vi = __shfl_sync(0xffffffffu, act, lb + 0);
        float vf = __shfl_sync(0xffffffffu, act, lb + 1);
        float vg = __shfl_sync(0xffffffffu, act, lb + 2);
        float vo = __shfl_sync(0xffffffffu, act, lb + 3);
        c = fmaf(vf, c, vi * vg);
        float h = vo * tanh_(c);
        if (gate == 0) h2s[1][u] = h;                 // h2(2047)
    }
    __syncthreads();

    // ---- FC head on h2(2047)
    if (tid < OUT_DIM) {
        float s = bfc[tid];
        const float *wf = Wfc + tid * HID;
#pragma unroll
        for (int kk = 0; kk < HID; kk++) s = fmaf(wf[kk], h2s[1][kk], s);
        out[b * OUT_DIM + tid] = s;
    }
}

extern "C" void kernel_launch(void* const* d_in, const int* in_sizes, int n_in,
                              void* d_out, int out_size) {
    (void)in_sizes; (void)n_in; (void)out_size;
    const float *X    = (const float *)d_in[0];
    const float *Wih0 = (const float *)d_in[1];
    const float *Whh0 = (const float *)d_in[2];
    const float *bih0 = (const float *)d_in[3];
    const float *bhh0 = (const float *)d_in[4];
    const float *Wih1 = (const float *)d_in[5];
    const float *Whh1 = (const float *)d_in[6];
    const float *bih1 = (const float *)d_in[7];
    const float *bhh1 = (const float *)d_in[8];
    const float *Wfc  = (const float *)d_in[9];
    const float *bfc  = (const float *)d_in[10];

    dim3 pg(8, BATCH);
    xg_prepass<<<pg, 128>>>(X, Wih0, bih0, bhh0);
    lstm_rec<<<BATCH, 256>>>(Whh0, Wih1, Whh1, bih1, bhh1, Wfc, bfc, (float *)d_out);
}

// round 7
// speedup vs baseline: 2.1139x; 2.1139x over previous
#include <cuda_runtime.h>

#define T_STEPS 2048
#define OUT_DIM 8
#define BATCH 512

typedef unsigned long long ull;

// staging for precomputed layer-1 input projection, layout [b][t][unit][gate]
__device__ float g_xg[(size_t)BATCH * T_STEPS * 128];

// ---- packed fp32x2 helpers (sm_100+) ----
__device__ __forceinline__ void fma2(ull &d, ull a, ull b) {
    asm("fma.rn.f32x2 %0, %1, %2, %0;" : "+l"(d) : "l"(a), "l"(b));
}
__device__ __forceinline__ ull add2(ull a, ull b) {
    ull r; asm("add.rn.f32x2 %0, %1, %2;" : "=l"(r) : "l"(a), "l"(b)); return r;
}
__device__ __forceinline__ float red2(ull a) {
    float lo, hi;
    asm("mov.b64 {%0,%1}, %2;" : "=f"(lo), "=f"(hi) : "l"(a));
    return lo + hi;
}
__device__ __forceinline__ void lds2(ull &a, ull &b, unsigned addr) {
    asm volatile("ld.shared.v2.b64 {%0,%1}, [%2];" : "=l"(a), "=l"(b) : "r"(addr));
}

__device__ __forceinline__ float sigm(float x) {
    return __fdividef(1.0f, 1.0f + __expf(-x));
}
__device__ __forceinline__ float tanh_(float x) {
    float e = __expf(2.0f * fminf(x, 15.0f));
    return __fdividef(e - 1.0f, e + 1.0f);
}

// =====================================================================
// prepass: g_xg[b][t][u][g] = (bih0+bhh0)[g*32+u] + Wih0[g*32+u,:] . x[b,t,:]
// grid 512 (=b), block 64. Thread j owns output channels o0=2j, o1=2j+1.
// =====================================================================
__global__ void __launch_bounds__(64) xg_prepass(
    const float *__restrict__ X, const float *__restrict__ Wih0,
    const float *__restrict__ bih0, const float *__restrict__ bhh0)
{
    __shared__ __align__(16) float xt[32 * 32];   // 32 timesteps x 32 features
    const int j = threadIdx.x;
    const int b = blockIdx.x;
    const int o0 = 2 * j, o1 = o0 + 1;
    const int r0 = (o0 & 3) * 32 + (o0 >> 2);
    const int r1 = (o1 & 3) * 32 + (o1 >> 2);

    ull w0[16], w1[16];
    {
        const ull *p = (const ull *)(Wih0 + r0 * 32);
#pragma unroll
        for (int i = 0; i < 16; i++) w0[i] = p[i];
        p = (const ull *)(Wih0 + r1 * 32);
#pragma unroll
        for (int i = 0; i < 16; i++) w1[i] = p[i];
    }
    const float bs0 = bih0[r0] + bhh0[r0];
    const float bs1 = bih0[r1] + bhh0[r1];

    const float *xb = X + (size_t)b * T_STEPS * 32;
    float *outp = g_xg + (size_t)b * T_STEPS * 128;
    const unsigned xtb = (unsigned)__cvta_generic_to_shared(xt);

    for (int tt = 0; tt < T_STEPS; tt += 32) {
        __syncthreads();
        const float4 *src = (const float4 *)(xb + tt * 32);
        float4 *dst4 = (float4 *)xt;
#pragma unroll
        for (int k = 0; k < 4; k++) dst4[j + k * 64] = src[j + k * 64];
        __syncthreads();

#pragma unroll 2
        for (int t = 0; t < 32; t++) {
            ull a0 = 0ull, a1 = 0ull, c0 = 0ull, c1 = 0ull;
#pragma unroll
            for (int i = 0; i < 4; i++) {
                ull p0, p1, p2, p3;
                lds2(p0, p1, xtb + (unsigned)(t * 128 + i * 32));
                lds2(p2, p3, xtb + (unsigned)(t * 128 + i * 32 + 16));
                fma2(a0, w0[4 * i + 0], p0); fma2(a1, w0[4 * i + 1], p1);
                fma2(a0, w0[4 * i + 2], p2); fma2(a1, w0[4 * i + 3], p3);
                fma2(c0, w1[4 * i + 0], p0); fma2(c1, w1[4 * i + 1], p1);
                fma2(c0, w1[4 * i + 2], p2); fma2(c1, w1[4 * i + 3], p3);
            }
            float2 vv;
            vv.x = red2(add2(a0, a1)) + bs0;
            vv.y = red2(add2(c0, c1)) + bs1;
            *(float2 *)(outp + (size_t)(tt + t) * 128 + o0) = vv;
        }
    }
}

// =====================================================================
// recurrent kernel: 64 threads = 1 batch element, single wave.
// warp 0: gate rows {i,f}; warp 1: gate rows {g,o}. 2 rows/lane, both layers.
// 3 tiny 2-warp barriers per step; no shfl.
// =====================================================================
__global__ void __launch_bounds__(64, 4) lstm_rec(
    const float *__restrict__ Whh0,
    const float *__restrict__ Wih1, const float *__restrict__ Whh1,
    const float *__restrict__ bih1, const float *__restrict__ bhh1,
    const float *__restrict__ Wfc, const float *__restrict__ bfc,
    float *__restrict__ out)
{
    __shared__ __align__(16) float h1s[32];
    __shared__ __align__(16) float h2s[32];
    __shared__ __align__(16) float xb0[32];
    __shared__ __align__(16) float xb1[32];

    const int tid = threadIdx.x;
    const int b = blockIdx.x;
    const int w = tid >> 5;           // 0: gates i,f   1: gates g,o
    const int u = tid & 31;           // hidden unit
    const int rA = (2 * w) * 32 + u;  // first owned gate row
    const int rB = rA + 32;           // second owned gate row

    // ---- register-resident weights: 6 rows x 32 = 96 ull = 192 regs ----
    ull wh0A[16], wh0B[16], wi1A[16], wi1B[16], wh1A[16], wh1B[16];
    {
        const ull *p;
        p = (const ull *)(Whh0 + rA * 32);
#pragma unroll
        for (int i = 0; i < 16; i++) wh0A[i] = p[i];
        p = (const ull *)(Whh0 + rB * 32);
#pragma unroll
        for (int i = 0; i < 16; i++) wh0B[i] = p[i];
        p = (const ull *)(Wih1 + rA * 32);
#pragma unroll
        for (int i = 0; i < 16; i++) wi1A[i] = p[i];
        p = (const ull *)(Wih1 + rB * 32);
#pragma unroll
        for (int i = 0; i < 16; i++) wi1B[i] = p[i];
        p = (const ull *)(Whh1 + rA * 32);
#pragma unroll
        for (int i = 0; i < 16; i++) wh1A[i] = p[i];
        p = (const ull *)(Whh1 + rB * 32);
#pragma unroll
        for (int i = 0; i < 16; i++) wh1B[i] = p[i];
    }
    const float b2A = bih1[rA] + bhh1[rA];
    const float b2B = bih1[rB] + bhh1[rB];

    // xg stream: float4 per (t, u)
    const float4 *xgp = (const float4 *)(g_xg + (size_t)b * T_STEPS * 128) + u;
    float4 cur = __ldg(xgp);
    float4 nxt = __ldg(xgp + 32);

    if (tid < 32) { h1s[tid] = 0.0f; h2s[tid] = 0.0f; }
    float c = 0.0f;                   // warp0: c1   warp1: c2

    const unsigned h1b = (unsigned)__cvta_generic_to_shared(h1s);
    const unsigned h2b = (unsigned)__cvta_generic_to_shared(h2s);
    __syncthreads();

#pragma unroll 1
    for (int t = 0; t < T_STEPS; t++) {
        // prefetch xg(t+2)
        float4 pre;
        {
            int tf = t + 2; if (tf > T_STEPS - 1) tf = T_STEPS - 1;
            pre = __ldg(xgp + (size_t)tf * 32);
        }

        // ===== phase A: layer-1 gates (rows rA,rB over h1(t-1)) =====
        ull a0 = 0ull, a1 = 0ull, d0 = 0ull, d1 = 0ull;
#pragma unroll
        for (int i = 0; i < 4; i++) {
            ull p0, p1, p2, p3;
            lds2(p0, p1, h1b + (unsigned)(i * 32));
            lds2(p2, p3, h1b + (unsigned)(i * 32 + 16));
            fma2(a0, wh0A[4 * i + 0], p0); fma2(a1, wh0A[4 * i + 1], p1);
            fma2(a0, wh0A[4 * i + 2], p2); fma2(a1, wh0A[4 * i + 3], p3);
            fma2(d0, wh0B[4 * i + 0], p0); fma2(d1, wh0B[4 * i + 1], p1);
            fma2(d0, wh0B[4 * i + 2], p2); fma2(d1, wh0B[4 * i + 3], p3);
        }
        float g0 = red2(add2(a0, a1)) + (w ? cur.z : cur.x);
        float g1 = red2(add2(d0, d1)) + (w ? cur.w : cur.y);
        float act0 = w ? tanh_(g0) : sigm(g0);   // w0: i     w1: g
        float act1 = sigm(g1);                   // w0: f     w1: o
        if (w) { xb0[u] = act0; xb1[u] = act1; }
        __syncthreads();                         // bar 1

        // ===== phase B (warp 0): c1/h1 update =====
        if (!w) {
            float vg = xb0[u], vo = xb1[u];
            c = fmaf(act1, c, act0 * vg);        // c1 = f*c1 + i*g
            h1s[u] = vo * tanh_(c);
        }
        __syncthreads();                         // bar 2

        // ===== phase C: layer-2 gates (rows rA,rB over [h1(t) | h2(t-1)]) =====
        a0 = 0ull; a1 = 0ull; d0 = 0ull; d1 = 0ull;
#pragma unroll
        for (int i = 0; i < 4; i++) {
            ull p0, p1, p2, p3;
            lds2(p0, p1, h1b + (unsigned)(i * 32));
            lds2(p2, p3, h1b + (unsigned)(i * 32 + 16));
            fma2(a0, wi1A[4 * i + 0], p0); fma2(a1, wi1A[4 * i + 1], p1);
            fma2(a0, wi1A[4 * i + 2], p2); fma2(a1, wi1A[4 * i + 3], p3);
            fma2(d0, wi1B[4 * i + 0], p0); fma2(d1, wi1B[4 * i + 1], p1);
            fma2(d0, wi1B[4 * i + 2], p2); fma2(d1, wi1B[4 * i + 3], p3);
        }
#pragma unroll
        for (int i = 0; i < 4; i++) {
            ull p0, p1, p2, p3;
            lds2(p0, p1, h2b + (unsigned)(i * 32));
            lds2(p2, p3, h2b + (unsigned)(i * 32 + 16));
            fma2(a0, wh1A[4 * i + 0], p0); fma2(a1, wh1A[4 * i + 1], p1);
            fma2(a0, wh1A[4 * i + 2], p2); fma2(a1, wh1A[4 * i + 3], p3);
            fma2(d0, wh1B[4 * i + 0], p0); fma2(d1, wh1B[4 * i + 1], p1);
            fma2(d0, wh1B[4 * i + 2], p2); fma2(d1, wh1B[4 * i + 3], p3);
        }
        g0 = red2(add2(a0, a1)) + b2A;
        g1 = red2(add2(d0, d1)) + b2B;
        act0 = w ? tanh_(g0) : sigm(g0);
        act1 = sigm(g1);
        if (!w) { xb0[u] = act0; xb1[u] = act1; }
        __syncthreads();                         // bar 3

        // ===== phase D (warp 1): c2/h2 update =====
        if (w) {
            float vi = xb0[u], vf = xb1[u];
            c = fmaf(vf, c, vi * act0);          // c2 = f*c2 + i*g
            h2s[u] = act1 * tanh_(c);
        }
        // next step's bar 1 makes h2s/xb visible before their next use

        cur = nxt; nxt = pre;
    }
    __syncthreads();

    // ===== FC head on h2(T-1) =====
    if (tid < OUT_DIM) {
        float s = bfc[tid];
        const float *wf = Wfc + tid * 32;
#pragma unroll
        for (int k = 0; k < 32; k++) s = fmaf(wf[k], h2s[k], s);
        out[b * OUT_DIM + tid] = s;
    }
}

extern "C" void kernel_launch(void* const* d_in, const int* in_sizes, int n_in,
                              void* d_out, int out_size) {
    (void)in_sizes; (void)n_in; (void)out_size;
    const float *X    = (const float *)d_in[0];
    const float *Wih0 = (const float *)d_in[1];
    const float *Whh0 = (const float *)d_in[2];
    const float *bih0 = (const float *)d_in[3];
    const float *bhh0 = (const float *)d_in[4];
    const float *Wih1 = (const float *)d_in[5];
    const float *Whh1 = (const float *)d_in[6];
    const float *bih1 = (const float *)d_in[7];
    const float *bhh1 = (const float *)d_in[8];
    const float *Wfc  = (const float *)d_in[9];
    const float *bfc  = (const float *)d_in[10];

    xg_prepass<<<BATCH, 64>>>(X, Wih0, bih0, bhh0);
    lstm_rec<<<BATCH, 64>>>(Whh0, Wih1, Whh1, bih1, bhh1, Wfc, bfc, (float *)d_out);
}